// round 15
// baseline (speedup 1.0000x reference)
#include <cuda_runtime.h>
#include <cuda_fp16.h>
#include <cstdint>

#define A_N 100000
#define B_N 200000
#define NBN 6
#define FA 133
#define FB 147
#define H 256
#define M_N 5000
#define DEPTH 4

// ---------------- device scratch (no allocations allowed) ----------------
__device__ float g_input_atom[(size_t)A_N * H];
__device__ float g_input_bond[(size_t)B_N * H];
__device__ float g_message_atom[(size_t)A_N * H];
__device__ float g_mb0[(size_t)B_N * H];
__device__ float g_mb1[(size_t)B_N * H];
__device__ float g_agg[(size_t)A_N * H];
__device__ float g_h1[(size_t)A_N * H];
__device__ float g_ah[(size_t)A_N * H];
__device__ int   g_offsets[M_N];

// dynamic range tracking (float bits stored as int; all values >= 0)
// slots: 0=input_bond 1=mb_l0 2=mb_l1 3=ma_d0 4=ma_d1 5=ma_d2 6=agg 7=h1 8=input_atom
__device__ int g_amax[9];

// pre-formatted B weights (fp16 hi/lo packed fragments).
// region = (ny, kb16): 2048 uint32. idx = ((nig*32)+lane)*4 + slot,
// slot = {bh_k0..7, bh_k8..15, bl_k0..7, bl_k8..15}, each uint32 = fp16x2.
// regions per weight = 2 * KB16 (KB16 padded EVEN so BK=32 stages are whole)
#define OFF_WIA 0        // 2*10 regions (padded from 9)
#define OFF_WIB 40960    // 2*10
#define OFF_WH  81920    // 3 * 2*16
#define OFF_WLR 278528   // 2*48
#define OFF_WO  475136   // 2*16
#define FMT_TOTAL 540672
__device__ uint32_t g_fmt[FMT_TOTAL];

static inline int cdiv(int a, int b) { return (a + b - 1) / b; }

// ================= helpers =================
__device__ __forceinline__ uint32_t smem_u32(const void* p) {
    uint32_t a;
    asm("{ .reg .u64 t; cvta.to.shared.u64 t, %1; cvt.u32.u64 %0, t; }" : "=r"(a) : "l"(p));
    return a;
}
__device__ __forceinline__ void split_f16(float x, __half& h, __half& l) {
    h = __float2half_rn(x);
    l = __float2half_rn(x - __half2float(h));
}
__device__ __forceinline__ void mma_f16(float* c, const uint32_t* a, const uint32_t* b) {
    asm volatile(
        "mma.sync.aligned.m16n8k16.row.col.f32.f16.f16.f32 "
        "{%0,%1,%2,%3}, {%4,%5,%6,%7}, {%8,%9}, {%0,%1,%2,%3};\n"
        : "+f"(c[0]), "+f"(c[1]), "+f"(c[2]), "+f"(c[3])
        : "r"(a[0]), "r"(a[1]), "r"(a[2]), "r"(a[3]), "r"(b[0]), "r"(b[1]));
}
__device__ __forceinline__ void cp16(uint32_t dst, const void* src) {
    asm volatile("cp.async.cg.shared.global [%0], [%1], 16;" :: "r"(dst), "l"(src));
}
// block-level max reduce (256 threads) + one atomicMax into g_amax[slot]
__device__ __forceinline__ void block_amax(float v, float* red, int slot) {
    const int lane = threadIdx.x & 31, wid = threadIdx.x >> 5;
#pragma unroll
    for (int off = 16; off; off >>= 1)
        v = fmaxf(v, __shfl_xor_sync(0xFFFFFFFFu, v, off));
    if (lane == 0) red[wid] = v;
    __syncthreads();
    if (wid == 0) {
        float m = (lane < 8) ? red[lane] : 0.f;
#pragma unroll
        for (int off = 4; off; off >>= 1)
            m = fmaxf(m, __shfl_xor_sync(0xFFFFFFFFu, m, off));
        if (lane == 0) atomicMax(&g_amax[slot], __float_as_int(m));
    }
}

__global__ void init_amax()
{
    if (threadIdx.x < 9) g_amax[threadIdx.x] = 0;
}

// ================= weight prep: fp16 split + fragment layout ===============
// region rb (within a weight) = ny*KB16 + kb16; out-of-range k -> zeros.
// WIA [0,20) KB=10, WIB [20,40) KB=10, WH [40,136), WLR [136,232), WO [232,264)
__global__ __launch_bounds__(128)
void prep_all(const float* __restrict__ W_ia, const float* __restrict__ W_ib,
              const float* __restrict__ W_h,  const float* __restrict__ W_lr,
              const float* __restrict__ W_o,  int rb_base)
{
    const int rb_g = rb_base + blockIdx.x;
    const float* W; int K, KB; long dstoff; int rb;
    if (rb_g < 20)       { W = W_ia; K = FA;    KB = 10; dstoff = OFF_WIA; rb = rb_g; }
    else if (rb_g < 40)  { W = W_ib; K = FB;    KB = 10; dstoff = OFF_WIB; rb = rb_g - 20; }
    else if (rb_g < 136) { int d = (rb_g - 40) >> 5;
                           W = W_h + (long)d * H * H; K = H; KB = 16;
                           dstoff = OFF_WH + (long)d * 65536; rb = (rb_g - 40) & 31; }
    else if (rb_g < 232) { W = W_lr; K = 3 * H; KB = 48; dstoff = OFF_WLR; rb = rb_g - 136; }
    else                 { W = W_o;  K = H;     KB = 16; dstoff = OFF_WO;  rb = rb_g - 232; }

    const int ny = rb / KB, kb = rb % KB;
    const int t = threadIdx.x;
    uint32_t* dst = g_fmt + dstoff + (long)rb * 2048;
#pragma unroll
    for (int i = 0; i < 16; i++) {
        int idx = i * 128 + t;
        int slot = idx & 3;
        int lane = (idx >> 2) & 31;
        int nig  = idx >> 7;                       // 0..15
        int n = ny * 128 + nig * 8 + (lane >> 2);
        int khalf = slot & 1;
        int k0 = kb * 16 + khalf * 8 + (lane & 3) * 2;
        float v0 = (k0 < K)     ? W[(long)k0 * 256 + n]       : 0.f;
        float v1 = (k0 + 1 < K) ? W[(long)(k0 + 1) * 256 + n] : 0.f;
        __half h0, l0, h1, l1;
        split_f16(v0, h0, l0);
        split_f16(v1, h1, l1);
        __half2 p = (slot >> 1) ? __halves2half2(l0, l1) : __halves2half2(h0, h1);
        dst[idx] = *(uint32_t*)&p;
    }
}

// ================= mma.sync fp16x3 GEMM, BK=32 double-buffered ==============
// C[M,256] = op(A)[M,K] @ B[K,256]; CTA: 128 rows x 128 cols (grid.y = n-half)
// 256 threads = 8 warps, layout 4 (m) x 2 (n): warp tile 32x64.
// Each pipeline stage = 32 k (two k16 sub-blocks) -> half the syncs/waits of
// BK=16 and 96 back-to-back mma per stage. __launch_bounds__(256,2): 2 CTA/SM.
// Dynamic smem (64KB): A stages [0,8192) u32 (stage buf at buf*4096; per sub:
// hi 1024 + lo 1024), B stages [8192,16384) (stage buf at 8192+buf*4096).
// A scaled by 1/s at staging (s = sum(g_amax)/32768), mask-truncation split.
// kb3 = leading k32-blocks with full 3-term split; kb >= kb3 -> 1-term.
// MODE 0: plain A scalar loads (ragged K), relu
// MODE 1: A = ma[b2a[r]] - mbprev[b2revb[r]], relu(addp + C)
// MODE 2: A from 3 sources (K=768), plain store
// MODE 3: plain A, relu(C + bias)
template<int MODE>
__global__ __launch_bounds__(256, 2)
void gemm_mma(const float* __restrict__ Ap, const float* __restrict__ A2,
              const float* __restrict__ A3,
              const int* __restrict__ gi1, const int* __restrict__ gi2,
              const uint32_t* __restrict__ fmt,
              float* __restrict__ Cp, const float* __restrict__ addp,
              const float* __restrict__ biasp, int M, int K,
              int KB32, int KB16, int kb3,
              int sa, int sb, int sc, int out_slot)
{
    extern __shared__ uint32_t sm[];
    __shared__ float red[8];

    const int tid = threadIdx.x;
    const int lane = tid & 31;
    const int wid = tid >> 5;
    const int wm = wid & 3;          // 0..3 (m groups of 32 rows)
    const int wn = wid >> 2;         // 0..1 (n halves of 64 cols)
    const int m0 = blockIdx.x * 128;
    const int n0 = blockIdx.y * 128;

    // dynamic scale
    float s = 1.f, inv_s = 1.f;
    if (sa >= 0) {
        float sum = __int_as_float(g_amax[sa]);
        if (sb >= 0) sum += __int_as_float(g_amax[sb]);
        if (sc >= 0) sum += __int_as_float(g_amax[sc]);
        s = fmaxf(sum, 1e-20f) * (1.f / 32768.f);
        inv_s = 1.f / s;
    }

    // staging identity: thread stages row srow; skh picks the k16 SUB-BLOCK
    const int srow = tid >> 1;
    const int skh = tid & 1;
    const int gm_s = min(m0 + srow, M - 1);
    int ia = 0, ir = 0;
    if (MODE == 1) { ia = gi1[gm_s]; ir = gi2[gm_s]; }

    // STS base u32-index within the sub-block plane (add h*2 + 4*t per pair)
    const int sts0 = skh * 2048
                   + (((srow >> 4) * 32 + ((srow & 7) << 2)) * 4)
                   + ((srow >> 3) & 1);

    float acc[2][8][4];
#pragma unroll
    for (int mi = 0; mi < 2; mi++)
#pragma unroll
        for (int ni = 0; ni < 8; ni++)
#pragma unroll
            for (int q = 0; q < 4; q++) acc[mi][ni][q] = 0.f;

    float areg[8];

    // load 8 A values: global k base = kb*32 + skh*16 + h*8
    auto loadA = [&](int kb, int h) {
        const int kbase = kb * 32 + skh * 16 + h * 8;
        if (MODE == 0) {
            const float* row = Ap + (long)gm_s * K + kbase;
#pragma unroll
            for (int j = 0; j < 8; j++) areg[j] = (kbase + j < K) ? row[j] * inv_s : 0.f;
        } else if (MODE == 1) {
            const float* ra = Ap + ((long)ia << 8) + kbase;
            const float* rr = A2 + ((long)ir << 8) + kbase;
            float4 x0 = *(const float4*)ra, x1 = *(const float4*)(ra + 4);
            float4 y0 = *(const float4*)rr, y1 = *(const float4*)(rr + 4);
            areg[0] = (x0.x - y0.x) * inv_s; areg[1] = (x0.y - y0.y) * inv_s;
            areg[2] = (x0.z - y0.z) * inv_s; areg[3] = (x0.w - y0.w) * inv_s;
            areg[4] = (x1.x - y1.x) * inv_s; areg[5] = (x1.y - y1.y) * inv_s;
            areg[6] = (x1.z - y1.z) * inv_s; areg[7] = (x1.w - y1.w) * inv_s;
        } else if (MODE == 2) {
            int which = kb >> 3;
            const float* src = (which == 0) ? Ap : (which == 1) ? A2 : A3;
            const float* ra = src + ((long)gm_s << 8) + (kb & 7) * 32 + skh * 16 + h * 8;
            float4 x0 = *(const float4*)ra, x1 = *(const float4*)(ra + 4);
            areg[0] = x0.x * inv_s; areg[1] = x0.y * inv_s;
            areg[2] = x0.z * inv_s; areg[3] = x0.w * inv_s;
            areg[4] = x1.x * inv_s; areg[5] = x1.y * inv_s;
            areg[6] = x1.z * inv_s; areg[7] = x1.w * inv_s;
        } else {
            const float* ra = Ap + ((long)gm_s << 8) + kbase;
            float4 x0 = *(const float4*)ra, x1 = *(const float4*)(ra + 4);
            areg[0] = x0.x * inv_s; areg[1] = x0.y * inv_s;
            areg[2] = x0.z * inv_s; areg[3] = x0.w * inv_s;
            areg[4] = x1.x * inv_s; areg[5] = x1.y * inv_s;
            areg[6] = x1.z * inv_s; areg[7] = x1.w * inv_s;
        }
    };

    // copy 2 consecutive k16 B regions (4096 u32) into the B stage
    auto issueB = [&](int kb, int buf) {
        const float4* src = (const float4*)(fmt + (long)(blockIdx.y * KB16 + kb * 2) * 2048);
        uint32_t dst = smem_u32(sm) + (8192 + buf * 4096) * 4;
#pragma unroll
        for (int i = 0; i < 4; i++) {
            int idx = i * 256 + tid;
            cp16(dst + idx * 16, src + idx);
        }
        asm volatile("cp.async.commit_group;" ::: "memory");
    };

    // mask-truncation split + store 4 packed pairs (one 8-k half of the sub)
    auto storeA = [&](int buf, int h) {
        uint32_t* As_ = sm + buf * 4096;
        const int base = sts0 + h * 2;
#pragma unroll
        for (int t = 0; t < 4; t++) {
            float x0 = areg[t * 2 + 0];
            float x1 = areg[t * 2 + 1];
            float h0 = __uint_as_float(__float_as_uint(x0) & 0xFFFFE000u);
            float h1 = __uint_as_float(__float_as_uint(x1) & 0xFFFFE000u);
            __half2 ph = __floats2half2_rn(h0, h1);
            __half2 pl = __floats2half2_rn(x0 - h0, x1 - h1);
            As_[base + 4 * t]        = *(uint32_t*)&ph;
            As_[base + 1024 + 4 * t] = *(uint32_t*)&pl;
        }
    };

    // 3-pass compute over one k16 sub-block
    auto compute_sub = [&](int buf, int sub, bool full3) {
        const uint32_t* a_s = sm + buf * 4096 + sub * 2048;
        const uint32_t* b_s = sm + 8192 + buf * 4096 + sub * 2048;
        uint4 bf[8];
#pragma unroll
        for (int ni = 0; ni < 8; ni++)
            bf[ni] = *(const uint4*)(b_s + ((wn * 8 + ni) * 32 + lane) * 4);
        uint4 ah4[2], al4[2];
#pragma unroll
        for (int mi = 0; mi < 2; mi++) {
            int mig = wm * 2 + mi;
            ah4[mi] = *(const uint4*)(a_s + (mig * 32 + lane) * 4);
            if (full3)
                al4[mi] = *(const uint4*)(a_s + 1024 + (mig * 32 + lane) * 4);
        }
#pragma unroll
        for (int ni = 0; ni < 8; ni++) {
            uint32_t bh[2] = {bf[ni].x, bf[ni].y};
#pragma unroll
            for (int mi = 0; mi < 2; mi++) {
                uint32_t a[4] = {ah4[mi].x, ah4[mi].y, ah4[mi].z, ah4[mi].w};
                mma_f16(acc[mi][ni], a, bh);
            }
        }
        if (full3) {
#pragma unroll
            for (int ni = 0; ni < 8; ni++) {
                uint32_t bl[2] = {bf[ni].z, bf[ni].w};
#pragma unroll
                for (int mi = 0; mi < 2; mi++) {
                    uint32_t a[4] = {ah4[mi].x, ah4[mi].y, ah4[mi].z, ah4[mi].w};
                    mma_f16(acc[mi][ni], a, bl);
                }
            }
#pragma unroll
            for (int ni = 0; ni < 8; ni++) {
                uint32_t bh[2] = {bf[ni].x, bf[ni].y};
#pragma unroll
                for (int mi = 0; mi < 2; mi++) {
                    uint32_t a[4] = {al4[mi].x, al4[mi].y, al4[mi].z, al4[mi].w};
                    mma_f16(acc[mi][ni], a, bh);
                }
            }
        }
    };

    // prologue: stage k32-block 0
    issueB(0, 0);
    loadA(0, 0);
    storeA(0, 0);
    loadA(0, 1);
    storeA(0, 1);
    asm volatile("cp.async.wait_group 0;" ::: "memory");
    __syncthreads();

    for (int kb = 0; kb < KB32; kb++) {
        const int buf = kb & 1;
        const bool more = (kb + 1 < KB32);
        const bool full3 = kb < kb3;
        if (more) { issueB(kb + 1, buf ^ 1); loadA(kb + 1, 0); }
        compute_sub(buf, 0, full3);
        if (more) { storeA(buf ^ 1, 0); loadA(kb + 1, 1); }
        compute_sub(buf, 1, full3);
        if (more) {
            storeA(buf ^ 1, 1);
            asm volatile("cp.async.wait_group 0;" ::: "memory");
        }
        __syncthreads();
    }

    // epilogue (scale back by s, fused add/bias/relu, track output amax)
    float wmax = 0.f;
#pragma unroll
    for (int mi = 0; mi < 2; mi++) {
        int r0 = m0 + wm * 32 + mi * 16 + (lane >> 2);
#pragma unroll
        for (int ni = 0; ni < 8; ni++) {
            int c = n0 + wn * 64 + ni * 8 + (lane & 3) * 2;
#pragma unroll
            for (int half = 0; half < 2; half++) {
                int r = r0 + half * 8;
                if (r >= M) continue;
                float x = acc[mi][ni][half * 2 + 0] * s;
                float y = acc[mi][ni][half * 2 + 1] * s;
                long o = (long)r * 256 + c;
                if (MODE == 1) {
                    float2 t = *(const float2*)(addp + o);
                    x += t.x; y += t.y;
                }
                if (MODE == 3) {
                    float2 t = *(const float2*)(biasp + c);
                    x += t.x; y += t.y;
                }
                if (MODE != 2) { x = fmaxf(x, 0.f); y = fmaxf(y, 0.f); }
                wmax = fmaxf(wmax, fmaxf(fabsf(x), fabsf(y)));
                *(float2*)(Cp + o) = make_float2(x, y);
            }
        }
    }
    if (out_slot >= 0) block_amax(wmax, red, out_slot);
}

// ---------------- sum*max neighbor aggregation (+ amax tracking) ----------
template<bool ADD>
__global__ __launch_bounds__(256)
void sum_max_kernel(const float* __restrict__ mb, const int* __restrict__ a2b,
                    const float* __restrict__ addsrc, float* __restrict__ outp,
                    int out_slot)
{
    __shared__ float red[8];
    int a = blockIdx.x * 4 + (threadIdx.x >> 6);
    float wmax = 0.f;
    if (a < A_N) {
        int h = (threadIdx.x & 63) << 2;
        const int* ab = a2b + (long)a * NBN;
        float4 s = make_float4(0.f, 0.f, 0.f, 0.f);
        float4 mx = make_float4(-1e30f, -1e30f, -1e30f, -1e30f);
#pragma unroll
        for (int j = 0; j < NBN; j++) {
            float4 v = *(const float4*)(mb + (long)ab[j] * H + h);
            s.x += v.x; s.y += v.y; s.z += v.z; s.w += v.w;
            mx.x = fmaxf(mx.x, v.x); mx.y = fmaxf(mx.y, v.y);
            mx.z = fmaxf(mx.z, v.z); mx.w = fmaxf(mx.w, v.w);
        }
        long o = (long)a * H + h;
        float4 r = make_float4(s.x * mx.x, s.y * mx.y, s.z * mx.z, s.w * mx.w);
        if (ADD) {
            float4 c = *(const float4*)(addsrc + o);
            r.x += c.x; r.y += c.y; r.z += c.z; r.w += c.w;
        }
        *(float4*)(outp + o) = r;
        wmax = fmaxf(fmaxf(fabsf(r.x), fabsf(r.y)), fmaxf(fabsf(r.z), fabsf(r.w)));
    }
    block_amax(wmax, red, out_slot);
}

// ---------------- exclusive scan of molecule sizes ----------------
__global__ void scan_kernel(const int* __restrict__ sizes)
{
    __shared__ int part[1024];
    int t = threadIdx.x;
    const int CH = (M_N + 1023) / 1024;
    int base = t * CH;
    int s = 0;
    for (int i = 0; i < CH; i++) {
        int idx = base + i;
        if (idx < M_N) s += sizes[idx];
    }
    part[t] = s;
    __syncthreads();
    for (int off = 1; off < 1024; off <<= 1) {
        int v = (t >= off) ? part[t - off] : 0;
        __syncthreads();
        part[t] += v;
        __syncthreads();
    }
    int run = (t == 0) ? 0 : part[t - 1];
    for (int i = 0; i < CH; i++) {
        int idx = base + i;
        if (idx < M_N) { g_offsets[idx] = run; run += sizes[idx]; }
    }
}

// ---------------- per-molecule mean pooling ----------------
__global__ __launch_bounds__(64)
void pool_kernel(const float* __restrict__ ah, const int* __restrict__ sizes,
                 float* __restrict__ out)
{
    int m = blockIdx.x;
    int h = threadIdx.x << 2;
    int start = g_offsets[m];
    int n = sizes[m];
    float4 s = make_float4(0.f, 0.f, 0.f, 0.f);
    for (int i = 0; i < n; i++) {
        float4 v = *(const float4*)(ah + (long)(start + i) * H + h);
        s.x += v.x; s.y += v.y; s.z += v.z; s.w += v.w;
    }
    float inv = 1.0f / (float)n;
    *(float4*)(out + (long)m * H + h) = make_float4(s.x * inv, s.y * inv, s.z * inv, s.w * inv);
}

// ---------------- launch ----------------
#define GEMM_SMEM 65536

extern "C" void kernel_launch(void* const* d_in, const int* in_sizes, int n_in,
                              void* d_out, int out_size)
{
    const float* f_atoms = (const float*)d_in[0];
    const float* f_bonds = (const float*)d_in[1];
    const float* W_ia    = (const float*)d_in[2];
    const float* W_ib    = (const float*)d_in[3];
    const float* W_h     = (const float*)d_in[4];
    const float* W_o     = (const float*)d_in[5];
    const float* b_o     = (const float*)d_in[6];
    const float* W_lr    = (const float*)d_in[7];
    const int*   a2b     = (const int*)d_in[8];
    const int*   b2a     = (const int*)d_in[9];
    const int*   b2revb  = (const int*)d_in[10];
    const int*   sizes   = (const int*)d_in[11];
    float* out = (float*)d_out;

    float *input_atom, *input_bond, *ma, *mb0, *mb1, *agg, *h1, *ah;
    uint32_t* fmt;
    cudaGetSymbolAddress((void**)&input_atom, g_input_atom);
    cudaGetSymbolAddress((void**)&input_bond, g_input_bond);
    cudaGetSymbolAddress((void**)&ma, g_message_atom);
    cudaGetSymbolAddress((void**)&mb0, g_mb0);
    cudaGetSymbolAddress((void**)&mb1, g_mb1);
    cudaGetSymbolAddress((void**)&agg, g_agg);
    cudaGetSymbolAddress((void**)&h1, g_h1);
    cudaGetSymbolAddress((void**)&ah, g_ah);
    cudaGetSymbolAddress((void**)&fmt, g_fmt);

    cudaFuncSetAttribute(gemm_mma<0>, cudaFuncAttributeMaxDynamicSharedMemorySize, GEMM_SMEM);
    cudaFuncSetAttribute(gemm_mma<1>, cudaFuncAttributeMaxDynamicSharedMemorySize, GEMM_SMEM);
    cudaFuncSetAttribute(gemm_mma<2>, cudaFuncAttributeMaxDynamicSharedMemorySize, GEMM_SMEM);
    cudaFuncSetAttribute(gemm_mma<3>, cudaFuncAttributeMaxDynamicSharedMemorySize, GEMM_SMEM);

    // reset amax slots (deterministic per launch/replay)
    init_amax<<<1, 32>>>();

    // weight prep: 264 regions total, 2 launches
    prep_all<<<132, 128>>>(W_ia, W_ib, W_h, W_lr, W_o, 0);
    prep_all<<<132, 128>>>(W_ia, W_ib, W_h, W_lr, W_o, 132);

    dim3 gA(cdiv(A_N, 128), 2), gB(cdiv(B_N, 128), 2);

    // input projections (relu); inputs ~N(0,1) -> s=1 (sa=-1)
    gemm_mma<0><<<gA, 256, GEMM_SMEM>>>(f_atoms, nullptr, nullptr, nullptr, nullptr,
                                        fmt + OFF_WIA, input_atom, nullptr, nullptr,
                                        A_N, FA, 5, 10, 5, -1, -1, -1, 8);
    gemm_mma<0><<<gB, 256, GEMM_SMEM>>>(f_bonds, nullptr, nullptr, nullptr, nullptr,
                                        fmt + OFF_WIB, input_bond, nullptr, nullptr,
                                        B_N, FB, 5, 10, 5, -1, -1, -1, 0);

    // message passing (ping-pong bond buffers), full 3-term fp16
    const float* mbcur = input_bond;
    for (int d = 0; d < DEPTH - 1; d++) {
        // ma amax -> slot 3+d
        sum_max_kernel<true><<<cdiv(A_N, 4), 256>>>(mbcur, a2b,
                                                    (d == 0) ? input_atom : ma, ma, 3 + d);
        float* mbout = (d % 2 == 0) ? mb0 : mb1;
        int mb_slot_in = (d == 0) ? 0 : d;           // ib=0, mb_l0=1, mb_l1=2
        int mb_slot_out = (d < 2) ? (1 + d) : -1;    // mb amax for next layer
        gemm_mma<1><<<gB, 256, GEMM_SMEM>>>(ma, mbcur, nullptr, b2a, b2revb,
                                            fmt + OFF_WH + (long)d * 65536,
                                            mbout, input_bond, nullptr,
                                            B_N, H, 8, 16, 8, 3 + d, mb_slot_in, -1, mb_slot_out);
        mbcur = mbout;
    }

    // final aggregation -> agg amax slot 6
    sum_max_kernel<false><<<cdiv(A_N, 4), 256>>>(mbcur, a2b, nullptr, agg, 6);

    // W_lr GEMM: scale = (agg + ma + ia)/32768; 3-term for agg slice (kb<8),
    // 1-term for the magnitude-dominated ma/ia slices
    gemm_mma<2><<<gA, 256, GEMM_SMEM>>>(agg, ma, input_atom, nullptr, nullptr,
                                        fmt + OFF_WLR, h1, nullptr, nullptr,
                                        A_N, 3 * H, 24, 48, 8, 6, 5, 8, 7);

    // W_o GEMM: scale = h1/32768, full 3-term fp16
    gemm_mma<3><<<gA, 256, GEMM_SMEM>>>(h1, nullptr, nullptr, nullptr, nullptr,
                                        fmt + OFF_WO, ah, nullptr, b_o,
                                        A_N, H, 8, 16, 8, 7, -1, -1, -1);

    scan_kernel<<<1, 1024>>>(sizes);
    pool_kernel<<<M_N, 64>>>(ah, sizes, out);
}

// round 16
// speedup vs baseline: 1.1716x; 1.1716x over previous
#include <cuda_runtime.h>
#include <cuda_fp16.h>
#include <cstdint>

#define A_N 100000
#define B_N 200000
#define NBN 6
#define FA 133
#define FB 147
#define H 256
#define M_N 5000
#define DEPTH 4

// ---------------- device scratch (no allocations allowed) ----------------
__device__ float g_input_atom[(size_t)A_N * H];
__device__ float g_input_bond[(size_t)B_N * H];
__device__ float g_message_atom[(size_t)A_N * H];
__device__ float g_mb0[(size_t)B_N * H];
__device__ float g_mb1[(size_t)B_N * H];
__device__ float g_agg[(size_t)A_N * H];
__device__ float g_h1[(size_t)A_N * H];
__device__ float g_ah[(size_t)A_N * H];
__device__ int   g_offsets[M_N];

// dynamic range tracking (float bits stored as int; all values >= 0)
// slots: 0=input_bond 1=mb_l0 2=mb_l1 3=ma_d0 4=ma_d1 5=ma_d2 6=agg 7=h1 8=input_atom
__device__ int g_amax[9];

// pre-formatted B weights (fp16 hi/lo packed fragments).
// region = (ny, kb16): 2048 uint32. idx = ((nig*32)+lane)*4 + slot,
// slot = {bh_k0..7, bh_k8..15, bl_k0..7, bl_k8..15}, each uint32 = fp16x2.
// regions per weight = 2 * ceil(K/16)
#define OFF_WIA 0        // 18 regions
#define OFF_WIB 36864    // 20
#define OFF_WH  77824    // 3 * 32
#define OFF_WLR 274432   // 96
#define OFF_WO  471040   // 32
#define FMT_TOTAL 536576
__device__ uint32_t g_fmt[FMT_TOTAL];

static inline int cdiv(int a, int b) { return (a + b - 1) / b; }

// ================= helpers =================
__device__ __forceinline__ uint32_t smem_u32(const void* p) {
    uint32_t a;
    asm("{ .reg .u64 t; cvta.to.shared.u64 t, %1; cvt.u32.u64 %0, t; }" : "=r"(a) : "l"(p));
    return a;
}
__device__ __forceinline__ void split_f16(float x, __half& h, __half& l) {
    h = __float2half_rn(x);
    l = __float2half_rn(x - __half2float(h));
}
__device__ __forceinline__ void mma_f16(float* c, const uint32_t* a, const uint32_t* b) {
    asm volatile(
        "mma.sync.aligned.m16n8k16.row.col.f32.f16.f16.f32 "
        "{%0,%1,%2,%3}, {%4,%5,%6,%7}, {%8,%9}, {%0,%1,%2,%3};\n"
        : "+f"(c[0]), "+f"(c[1]), "+f"(c[2]), "+f"(c[3])
        : "r"(a[0]), "r"(a[1]), "r"(a[2]), "r"(a[3]), "r"(b[0]), "r"(b[1]));
}
__device__ __forceinline__ void cp16(uint32_t dst, const void* src) {
    asm volatile("cp.async.cg.shared.global [%0], [%1], 16;" :: "r"(dst), "l"(src));
}
// block-level max reduce (256 threads) + one atomicMax into g_amax[slot]
__device__ __forceinline__ void block_amax(float v, float* red, int slot) {
    const int lane = threadIdx.x & 31, wid = threadIdx.x >> 5;
#pragma unroll
    for (int off = 16; off; off >>= 1)
        v = fmaxf(v, __shfl_xor_sync(0xFFFFFFFFu, v, off));
    if (lane == 0) red[wid] = v;
    __syncthreads();
    if (wid == 0) {
        float m = (lane < 8) ? red[lane] : 0.f;
#pragma unroll
        for (int off = 4; off; off >>= 1)
            m = fmaxf(m, __shfl_xor_sync(0xFFFFFFFFu, m, off));
        if (lane == 0) atomicMax(&g_amax[slot], __float_as_int(m));
    }
}

__global__ void init_amax()
{
    if (threadIdx.x < 9) g_amax[threadIdx.x] = 0;
}

// ================= weight prep: fp16 split + fragment layout ===============
// region rb (within a weight) = ny*KB + kb; global region id selects weight.
// WIA [0,18), WIB [18,38), WH [38,134), WLR [134,230), WO [230,262)
__global__ __launch_bounds__(128)
void prep_all(const float* __restrict__ W_ia, const float* __restrict__ W_ib,
              const float* __restrict__ W_h,  const float* __restrict__ W_lr,
              const float* __restrict__ W_o,  int rb_base)
{
    const int rb_g = rb_base + blockIdx.x;
    const float* W; int K, KB; long dstoff; int rb;
    if (rb_g < 18)       { W = W_ia; K = FA;    KB = 9;  dstoff = OFF_WIA; rb = rb_g; }
    else if (rb_g < 38)  { W = W_ib; K = FB;    KB = 10; dstoff = OFF_WIB; rb = rb_g - 18; }
    else if (rb_g < 134) { int d = (rb_g - 38) >> 5;
                           W = W_h + (long)d * H * H; K = H; KB = 16;
                           dstoff = OFF_WH + (long)d * 65536; rb = (rb_g - 38) & 31; }
    else if (rb_g < 230) { W = W_lr; K = 3 * H; KB = 48; dstoff = OFF_WLR; rb = rb_g - 134; }
    else                 { W = W_o;  K = H;     KB = 16; dstoff = OFF_WO;  rb = rb_g - 230; }

    const int ny = rb / KB, kb = rb % KB;
    const int t = threadIdx.x;
    uint32_t* dst = g_fmt + dstoff + (long)rb * 2048;
#pragma unroll
    for (int i = 0; i < 16; i++) {
        int idx = i * 128 + t;
        int slot = idx & 3;
        int lane = (idx >> 2) & 31;
        int nig  = idx >> 7;                       // 0..15
        int n = ny * 128 + nig * 8 + (lane >> 2);
        int khalf = slot & 1;
        int k0 = kb * 16 + khalf * 8 + (lane & 3) * 2;
        float v0 = (k0 < K)     ? W[(long)k0 * 256 + n]       : 0.f;
        float v1 = (k0 + 1 < K) ? W[(long)(k0 + 1) * 256 + n] : 0.f;
        __half h0, l0, h1, l1;
        split_f16(v0, h0, l0);
        split_f16(v1, h1, l1);
        __half2 p = (slot >> 1) ? __halves2half2(l0, l1) : __halves2half2(h0, h1);
        dst[idx] = *(uint32_t*)&p;
    }
}

// ================= mma.sync fp16x3 GEMM with dynamic scaling =================
// C[M,256] = op(A)[M,K] @ B[K,256]; CTA: 128 rows x 128 cols (grid.y = n-half)
// 256 threads = 8 warps, layout 4 (m) x 2 (n): warp tile 32x64.
// __launch_bounds__(256,2) pins regs <= 128 so 2 CTAs co-reside per SM.
// compute() hoists ALL fragment LDS up front and issues the 48 mma in 3
// passes over (ni, mi) so same-acc mma are separated by 15 independent ones.
// A scaled by 1/s at staging (s = sum(g_amax)/32768), mask-truncation split.
// kb3 = leading k-blocks with the full 3-term split; kb >= kb3 -> 1-term.
// MODE 0: plain A scalar loads (ragged K), relu
// MODE 1: A = ma[b2a[r]] - mbprev[b2revb[r]] (K=256), relu(addp + C)
// MODE 2: A from 3 sources (K=768), plain store
// MODE 3: plain A (K=256), relu(C + bias)
template<int MODE>
__global__ __launch_bounds__(256, 2)
void gemm_mma(const float* __restrict__ Ap, const float* __restrict__ A2,
              const float* __restrict__ A3,
              const int* __restrict__ gi1, const int* __restrict__ gi2,
              const uint32_t* __restrict__ fmt,
              float* __restrict__ Cp, const float* __restrict__ addp,
              const float* __restrict__ biasp, int M, int K, int KB, int kb3,
              int sa, int sb, int sc, int out_slot)
{
    // A fragments: hi plane [0..1023], lo plane [1024..2047]; idx=(mig*32+lane)*4+reg
    __shared__ uint32_t As[2][2048];
    // B fragments: idx=(nig*32+lane)*4+slot
    __shared__ uint32_t Bs[2][2048];
    __shared__ float red[8];

    const int tid = threadIdx.x;
    const int lane = tid & 31;
    const int wid = tid >> 5;
    const int wm = wid & 3;          // 0..3 (m groups of 32 rows)
    const int wn = wid >> 2;         // 0..1 (n halves of 64 cols)
    const int m0 = blockIdx.x * 128;
    const int n0 = blockIdx.y * 128;

    // dynamic scale
    float s = 1.f, inv_s = 1.f;
    if (sa >= 0) {
        float sum = __int_as_float(g_amax[sa]);
        if (sb >= 0) sum += __int_as_float(g_amax[sb]);
        if (sc >= 0) sum += __int_as_float(g_amax[sc]);
        s = fmaxf(sum, 1e-20f) * (1.f / 32768.f);
        inv_s = 1.f / s;
    }

    // staging identity: thread stages row srow, k-half skh (8 k each)
    const int srow = tid >> 1;
    const int skh = tid & 1;
    const int gm_s = min(m0 + srow, M - 1);
    int ia = 0, ir = 0;
    if (MODE == 1) { ia = gi1[gm_s]; ir = gi2[gm_s]; }

    // STS base u32-index; the 4 staged pairs land at sts0 + 4*t
    const int sts0 = (((srow >> 4) * 32 + ((srow & 7) << 2)) * 4)
                   + (skh * 2 + ((srow >> 3) & 1));

    float acc[2][8][4];
#pragma unroll
    for (int mi = 0; mi < 2; mi++)
#pragma unroll
        for (int ni = 0; ni < 8; ni++)
#pragma unroll
            for (int q = 0; q < 4; q++) acc[mi][ni][q] = 0.f;

    float areg[8];

    auto loadA = [&](int kb) {
        const int kbase = kb * 16 + skh * 8;
        if (MODE == 0) {
            const float* row = Ap + (long)gm_s * K + kbase;
#pragma unroll
            for (int j = 0; j < 8; j++) areg[j] = (kbase + j < K) ? row[j] * inv_s : 0.f;
        } else if (MODE == 1) {
            const float* ra = Ap + ((long)ia << 8) + kbase;
            const float* rr = A2 + ((long)ir << 8) + kbase;
            float4 x0 = *(const float4*)ra, x1 = *(const float4*)(ra + 4);
            float4 y0 = *(const float4*)rr, y1 = *(const float4*)(rr + 4);
            areg[0] = (x0.x - y0.x) * inv_s; areg[1] = (x0.y - y0.y) * inv_s;
            areg[2] = (x0.z - y0.z) * inv_s; areg[3] = (x0.w - y0.w) * inv_s;
            areg[4] = (x1.x - y1.x) * inv_s; areg[5] = (x1.y - y1.y) * inv_s;
            areg[6] = (x1.z - y1.z) * inv_s; areg[7] = (x1.w - y1.w) * inv_s;
        } else if (MODE == 2) {
            int which = kb >> 4;
            const float* src = (which == 0) ? Ap : (which == 1) ? A2 : A3;
            const float* ra = src + ((long)gm_s << 8) + (kb & 15) * 16 + skh * 8;
            float4 x0 = *(const float4*)ra, x1 = *(const float4*)(ra + 4);
            areg[0] = x0.x * inv_s; areg[1] = x0.y * inv_s;
            areg[2] = x0.z * inv_s; areg[3] = x0.w * inv_s;
            areg[4] = x1.x * inv_s; areg[5] = x1.y * inv_s;
            areg[6] = x1.z * inv_s; areg[7] = x1.w * inv_s;
        } else {
            const float* ra = Ap + ((long)gm_s << 8) + kbase;
            float4 x0 = *(const float4*)ra, x1 = *(const float4*)(ra + 4);
            areg[0] = x0.x * inv_s; areg[1] = x0.y * inv_s;
            areg[2] = x0.z * inv_s; areg[3] = x0.w * inv_s;
            areg[4] = x1.x * inv_s; areg[5] = x1.y * inv_s;
            areg[6] = x1.z * inv_s; areg[7] = x1.w * inv_s;
        }
    };

    auto issueB = [&](int kb, int buf) {
        const float4* src = (const float4*)(fmt + (long)(blockIdx.y * KB + kb) * 2048);
        uint32_t dst = smem_u32(&Bs[buf][0]);
#pragma unroll
        for (int i = 0; i < 2; i++) {
            int idx = i * 256 + tid;
            cp16(dst + idx * 16, src + idx);
        }
        asm volatile("cp.async.commit_group;" ::: "memory");
    };

    // mask-truncation split: hi = x with low 13 mantissa bits zeroed (exact f16),
    // lo = x - hi (one FADD). Packed pairs via single pack-convert.
    auto storeA = [&](int buf) {
#pragma unroll
        for (int t = 0; t < 4; t++) {
            float x0 = areg[t * 2 + 0];
            float x1 = areg[t * 2 + 1];
            float h0 = __uint_as_float(__float_as_uint(x0) & 0xFFFFE000u);
            float h1 = __uint_as_float(__float_as_uint(x1) & 0xFFFFE000u);
            __half2 ph = __floats2half2_rn(h0, h1);
            __half2 pl = __floats2half2_rn(x0 - h0, x1 - h1);
            As[buf][sts0 + 4 * t]        = *(uint32_t*)&ph;
            As[buf][1024 + sts0 + 4 * t] = *(uint32_t*)&pl;
        }
    };

    // 3-pass compute: hoisted loads, same-acc mma separated by 15 others.
    auto compute = [&](int buf, bool full3) {
        const uint32_t* a_s = As[buf];
        const uint32_t* b_s = Bs[buf];
        uint4 bf[8];
#pragma unroll
        for (int ni = 0; ni < 8; ni++)
            bf[ni] = *(const uint4*)(b_s + ((wn * 8 + ni) * 32 + lane) * 4);
        uint4 ah4[2], al4[2];
#pragma unroll
        for (int mi = 0; mi < 2; mi++) {
            int mig = wm * 2 + mi;
            ah4[mi] = *(const uint4*)(a_s + (mig * 32 + lane) * 4);
            if (full3)
                al4[mi] = *(const uint4*)(a_s + 1024 + (mig * 32 + lane) * 4);
        }
        // pass 1: ah * bh
#pragma unroll
        for (int ni = 0; ni < 8; ni++) {
            uint32_t bh[2] = {bf[ni].x, bf[ni].y};
#pragma unroll
            for (int mi = 0; mi < 2; mi++) {
                uint32_t a[4] = {ah4[mi].x, ah4[mi].y, ah4[mi].z, ah4[mi].w};
                mma_f16(acc[mi][ni], a, bh);
            }
        }
        if (full3) {
            // pass 2: ah * bl
#pragma unroll
            for (int ni = 0; ni < 8; ni++) {
                uint32_t bl[2] = {bf[ni].z, bf[ni].w};
#pragma unroll
                for (int mi = 0; mi < 2; mi++) {
                    uint32_t a[4] = {ah4[mi].x, ah4[mi].y, ah4[mi].z, ah4[mi].w};
                    mma_f16(acc[mi][ni], a, bl);
                }
            }
            // pass 3: al * bh
#pragma unroll
            for (int ni = 0; ni < 8; ni++) {
                uint32_t bh[2] = {bf[ni].x, bf[ni].y};
#pragma unroll
                for (int mi = 0; mi < 2; mi++) {
                    uint32_t a[4] = {al4[mi].x, al4[mi].y, al4[mi].z, al4[mi].w};
                    mma_f16(acc[mi][ni], a, bh);
                }
            }
        }
    };

    // prologue
    loadA(0);
    issueB(0, 0);
    storeA(0);
    asm volatile("cp.async.wait_group 0;" ::: "memory");
    __syncthreads();

    for (int kb = 0; kb < KB; kb++) {
        const int buf = kb & 1;
        const bool more = (kb + 1 < KB);
        if (more) { loadA(kb + 1); issueB(kb + 1, buf ^ 1); }
        compute(buf, kb < kb3);
        if (more) {
            storeA(buf ^ 1);
            asm volatile("cp.async.wait_group 0;" ::: "memory");
        }
        __syncthreads();
    }

    // epilogue (scale back by s, fused add/bias/relu, track output amax)
    float wmax = 0.f;
#pragma unroll
    for (int mi = 0; mi < 2; mi++) {
        int r0 = m0 + wm * 32 + mi * 16 + (lane >> 2);
#pragma unroll
        for (int ni = 0; ni < 8; ni++) {
            int c = n0 + wn * 64 + ni * 8 + (lane & 3) * 2;
#pragma unroll
            for (int half = 0; half < 2; half++) {
                int r = r0 + half * 8;
                if (r >= M) continue;
                float x = acc[mi][ni][half * 2 + 0] * s;
                float y = acc[mi][ni][half * 2 + 1] * s;
                long o = (long)r * 256 + c;
                if (MODE == 1) {
                    float2 t = *(const float2*)(addp + o);
                    x += t.x; y += t.y;
                }
                if (MODE == 3) {
                    float2 t = *(const float2*)(biasp + c);
                    x += t.x; y += t.y;
                }
                if (MODE != 2) { x = fmaxf(x, 0.f); y = fmaxf(y, 0.f); }
                wmax = fmaxf(wmax, fmaxf(fabsf(x), fabsf(y)));
                *(float2*)(Cp + o) = make_float2(x, y);
            }
        }
    }
    if (out_slot >= 0) block_amax(wmax, red, out_slot);
}

// ---------------- sum*max neighbor aggregation (+ amax tracking) ----------
template<bool ADD>
__global__ __launch_bounds__(256)
void sum_max_kernel(const float* __restrict__ mb, const int* __restrict__ a2b,
                    const float* __restrict__ addsrc, float* __restrict__ outp,
                    int out_slot)
{
    __shared__ float red[8];
    int a = blockIdx.x * 4 + (threadIdx.x >> 6);
    float wmax = 0.f;
    if (a < A_N) {
        int h = (threadIdx.x & 63) << 2;
        const int* ab = a2b + (long)a * NBN;
        float4 s = make_float4(0.f, 0.f, 0.f, 0.f);
        float4 mx = make_float4(-1e30f, -1e30f, -1e30f, -1e30f);
#pragma unroll
        for (int j = 0; j < NBN; j++) {
            float4 v = *(const float4*)(mb + (long)ab[j] * H + h);
            s.x += v.x; s.y += v.y; s.z += v.z; s.w += v.w;
            mx.x = fmaxf(mx.x, v.x); mx.y = fmaxf(mx.y, v.y);
            mx.z = fmaxf(mx.z, v.z); mx.w = fmaxf(mx.w, v.w);
        }
        long o = (long)a * H + h;
        float4 r = make_float4(s.x * mx.x, s.y * mx.y, s.z * mx.z, s.w * mx.w);
        if (ADD) {
            float4 c = *(const float4*)(addsrc + o);
            r.x += c.x; r.y += c.y; r.z += c.z; r.w += c.w;
        }
        *(float4*)(outp + o) = r;
        wmax = fmaxf(fmaxf(fabsf(r.x), fabsf(r.y)), fmaxf(fabsf(r.z), fabsf(r.w)));
    }
    block_amax(wmax, red, out_slot);
}

// ---------------- exclusive scan of molecule sizes ----------------
__global__ void scan_kernel(const int* __restrict__ sizes)
{
    __shared__ int part[1024];
    int t = threadIdx.x;
    const int CH = (M_N + 1023) / 1024;
    int base = t * CH;
    int s = 0;
    for (int i = 0; i < CH; i++) {
        int idx = base + i;
        if (idx < M_N) s += sizes[idx];
    }
    part[t] = s;
    __syncthreads();
    for (int off = 1; off < 1024; off <<= 1) {
        int v = (t >= off) ? part[t - off] : 0;
        __syncthreads();
        part[t] += v;
        __syncthreads();
    }
    int run = (t == 0) ? 0 : part[t - 1];
    for (int i = 0; i < CH; i++) {
        int idx = base + i;
        if (idx < M_N) { g_offsets[idx] = run; run += sizes[idx]; }
    }
}

// ---------------- per-molecule mean pooling ----------------
__global__ __launch_bounds__(64)
void pool_kernel(const float* __restrict__ ah, const int* __restrict__ sizes,
                 float* __restrict__ out)
{
    int m = blockIdx.x;
    int h = threadIdx.x << 2;
    int start = g_offsets[m];
    int n = sizes[m];
    float4 s = make_float4(0.f, 0.f, 0.f, 0.f);
    for (int i = 0; i < n; i++) {
        float4 v = *(const float4*)(ah + (long)(start + i) * H + h);
        s.x += v.x; s.y += v.y; s.z += v.z; s.w += v.w;
    }
    float inv = 1.0f / (float)n;
    *(float4*)(out + (long)m * H + h) = make_float4(s.x * inv, s.y * inv, s.z * inv, s.w * inv);
}

// ---------------- launch ----------------
extern "C" void kernel_launch(void* const* d_in, const int* in_sizes, int n_in,
                              void* d_out, int out_size)
{
    const float* f_atoms = (const float*)d_in[0];
    const float* f_bonds = (const float*)d_in[1];
    const float* W_ia    = (const float*)d_in[2];
    const float* W_ib    = (const float*)d_in[3];
    const float* W_h     = (const float*)d_in[4];
    const float* W_o     = (const float*)d_in[5];
    const float* b_o     = (const float*)d_in[6];
    const float* W_lr    = (const float*)d_in[7];
    const int*   a2b     = (const int*)d_in[8];
    const int*   b2a     = (const int*)d_in[9];
    const int*   b2revb  = (const int*)d_in[10];
    const int*   sizes   = (const int*)d_in[11];
    float* out = (float*)d_out;

    float *input_atom, *input_bond, *ma, *mb0, *mb1, *agg, *h1, *ah;
    uint32_t* fmt;
    cudaGetSymbolAddress((void**)&input_atom, g_input_atom);
    cudaGetSymbolAddress((void**)&input_bond, g_input_bond);
    cudaGetSymbolAddress((void**)&ma, g_message_atom);
    cudaGetSymbolAddress((void**)&mb0, g_mb0);
    cudaGetSymbolAddress((void**)&mb1, g_mb1);
    cudaGetSymbolAddress((void**)&agg, g_agg);
    cudaGetSymbolAddress((void**)&h1, g_h1);
    cudaGetSymbolAddress((void**)&ah, g_ah);
    cudaGetSymbolAddress((void**)&fmt, g_fmt);

    // reset amax slots (deterministic per launch/replay)
    init_amax<<<1, 32>>>();

    // weight prep: 262 regions total, 2 launches
    prep_all<<<131, 128>>>(W_ia, W_ib, W_h, W_lr, W_o, 0);
    prep_all<<<131, 128>>>(W_ia, W_ib, W_h, W_lr, W_o, 131);

    dim3 gA(cdiv(A_N, 128), 2), gB(cdiv(B_N, 128), 2);

    // atom input projection: 1-term fp16 (input_atom is additively dominated
    // by agg from depth 0 on; its rounding is ~7e-6 relative downstream)
    gemm_mma<0><<<gA, 256>>>(f_atoms, nullptr, nullptr, nullptr, nullptr,
                             fmt + OFF_WIA, input_atom, nullptr, nullptr,
                             A_N, FA, 9, 0, -1, -1, -1, 8);
    // bond input projection: full 3-term (base of the amplifying recurrence)
    gemm_mma<0><<<gB, 256>>>(f_bonds, nullptr, nullptr, nullptr, nullptr,
                             fmt + OFF_WIB, input_bond, nullptr, nullptr,
                             B_N, FB, 10, 10, -1, -1, -1, 0);

    // message passing (ping-pong bond buffers), full 3-term fp16
    const float* mbcur = input_bond;
    for (int d = 0; d < DEPTH - 1; d++) {
        // ma amax -> slot 3+d
        sum_max_kernel<true><<<cdiv(A_N, 4), 256>>>(mbcur, a2b,
                                                    (d == 0) ? input_atom : ma, ma, 3 + d);
        float* mbout = (d % 2 == 0) ? mb0 : mb1;
        int mb_slot_in = (d == 0) ? 0 : d;           // ib=0, mb_l0=1, mb_l1=2
        int mb_slot_out = (d < 2) ? (1 + d) : -1;    // mb amax for next layer
        gemm_mma<1><<<gB, 256>>>(ma, mbcur, nullptr, b2a, b2revb,
                                 fmt + OFF_WH + (long)d * 65536,
                                 mbout, input_bond, nullptr,
                                 B_N, H, 16, 16, 3 + d, mb_slot_in, -1, mb_slot_out);
        mbcur = mbout;
    }

    // final aggregation -> agg amax slot 6
    sum_max_kernel<false><<<cdiv(A_N, 4), 256>>>(mbcur, a2b, nullptr, agg, 6);

    // W_lr GEMM: scale = (agg + ma + ia)/32768; 3-term for agg slice (kb<16),
    // 1-term for the magnitude-dominated ma/ia slices
    gemm_mma<2><<<gA, 256>>>(agg, ma, input_atom, nullptr, nullptr,
                             fmt + OFF_WLR, h1, nullptr, nullptr,
                             A_N, 3 * H, 48, 16, 6, 5, 8, 7);

    // W_o GEMM: final linear stage — 1-term fp16 (error passes unamplified)
    gemm_mma<3><<<gA, 256>>>(h1, nullptr, nullptr, nullptr, nullptr,
                             fmt + OFF_WO, ah, nullptr, b_o,
                             A_N, H, 16, 0, 7, -1, -1, -1);

    scan_kernel<<<1, 1024>>>(sizes);
    pool_kernel<<<M_N, 64>>>(ah, sizes, out);
}

// round 17
// speedup vs baseline: 1.1929x; 1.0182x over previous
#include <cuda_runtime.h>
#include <cuda_fp16.h>
#include <cstdint>

#define A_N 100000
#define B_N 200000
#define NBN 6
#define FA 133
#define FB 147
#define H 256
#define M_N 5000
#define DEPTH 4

// ---------------- device scratch (no allocations allowed) ----------------
__device__ float g_input_atom[(size_t)A_N * H];
__device__ float g_input_bond[(size_t)B_N * H];
__device__ float g_message_atom[(size_t)A_N * H];
__device__ float g_mb0[(size_t)B_N * H];
__device__ float g_mb1[(size_t)B_N * H];
__device__ float g_agg[(size_t)A_N * H];
__device__ float g_h1[(size_t)A_N * H];
__device__ float g_ah[(size_t)A_N * H];
__device__ int   g_offsets[M_N];

// dynamic range tracking (float bits stored as int; all values >= 0)
// slots: 0=input_bond 1=mb_l0 2=mb_l1 3=ma_d0 4=ma_d1 5=ma_d2 6=agg 7=h1 8=input_atom
__device__ int g_amax[9];

// pre-formatted B weights (fp16 hi/lo packed fragments).
// region = (ny, kb16): 2048 uint32. idx = ((nig*32)+lane)*4 + slot,
// slot = {bh_k0..7, bh_k8..15, bl_k0..7, bl_k8..15}, each uint32 = fp16x2.
// regions per weight = 2 * ceil(K/16)
#define OFF_WIA 0        // 18 regions
#define OFF_WIB 36864    // 20
#define OFF_WH  77824    // 3 * 32
#define OFF_WLR 274432   // 96
#define OFF_WO  471040   // 32
#define FMT_TOTAL 536576
__device__ uint32_t g_fmt[FMT_TOTAL];

static inline int cdiv(int a, int b) { return (a + b - 1) / b; }

// ================= helpers =================
__device__ __forceinline__ uint32_t smem_u32(const void* p) {
    uint32_t a;
    asm("{ .reg .u64 t; cvta.to.shared.u64 t, %1; cvt.u32.u64 %0, t; }" : "=r"(a) : "l"(p));
    return a;
}
__device__ __forceinline__ void split_f16(float x, __half& h, __half& l) {
    h = __float2half_rn(x);
    l = __float2half_rn(x - __half2float(h));
}
__device__ __forceinline__ void mma_f16(float* c, const uint32_t* a, const uint32_t* b) {
    asm volatile(
        "mma.sync.aligned.m16n8k16.row.col.f32.f16.f16.f32 "
        "{%0,%1,%2,%3}, {%4,%5,%6,%7}, {%8,%9}, {%0,%1,%2,%3};\n"
        : "+f"(c[0]), "+f"(c[1]), "+f"(c[2]), "+f"(c[3])
        : "r"(a[0]), "r"(a[1]), "r"(a[2]), "r"(a[3]), "r"(b[0]), "r"(b[1]));
}
__device__ __forceinline__ void cp16(uint32_t dst, const void* src) {
    asm volatile("cp.async.cg.shared.global [%0], [%1], 16;" :: "r"(dst), "l"(src));
}
// block-level max reduce (256 threads) + one atomicMax into g_amax[slot]
__device__ __forceinline__ void block_amax(float v, float* red, int slot) {
    const int lane = threadIdx.x & 31, wid = threadIdx.x >> 5;
#pragma unroll
    for (int off = 16; off; off >>= 1)
        v = fmaxf(v, __shfl_xor_sync(0xFFFFFFFFu, v, off));
    if (lane == 0) red[wid] = v;
    __syncthreads();
    if (wid == 0) {
        float m = (lane < 8) ? red[lane] : 0.f;
#pragma unroll
        for (int off = 4; off; off >>= 1)
            m = fmaxf(m, __shfl_xor_sync(0xFFFFFFFFu, m, off));
        if (lane == 0) atomicMax(&g_amax[slot], __float_as_int(m));
    }
}

// ================= weight prep: fp16 split + fragment layout ===============
// region rb (within a weight) = ny*KB + kb; global region id selects weight.
// WIA [0,18), WIB [18,38), WH [38,134), WLR [134,230), WO [230,262)
// Block handling rb_g==0 also zeroes the g_amax slots (replaces init launch;
// safe: no kernel in this launch touches g_amax, gemms run strictly after).
__global__ __launch_bounds__(128)
void prep_all(const float* __restrict__ W_ia, const float* __restrict__ W_ib,
              const float* __restrict__ W_h,  const float* __restrict__ W_lr,
              const float* __restrict__ W_o,  int rb_base)
{
    const int rb_g = rb_base + blockIdx.x;
    if (rb_g == 0 && threadIdx.x < 9) g_amax[threadIdx.x] = 0;

    const float* W; int K, KB; long dstoff; int rb;
    if (rb_g < 18)       { W = W_ia; K = FA;    KB = 9;  dstoff = OFF_WIA; rb = rb_g; }
    else if (rb_g < 38)  { W = W_ib; K = FB;    KB = 10; dstoff = OFF_WIB; rb = rb_g - 18; }
    else if (rb_g < 134) { int d = (rb_g - 38) >> 5;
                           W = W_h + (long)d * H * H; K = H; KB = 16;
                           dstoff = OFF_WH + (long)d * 65536; rb = (rb_g - 38) & 31; }
    else if (rb_g < 230) { W = W_lr; K = 3 * H; KB = 48; dstoff = OFF_WLR; rb = rb_g - 134; }
    else                 { W = W_o;  K = H;     KB = 16; dstoff = OFF_WO;  rb = rb_g - 230; }

    const int ny = rb / KB, kb = rb % KB;
    const int t = threadIdx.x;
    uint32_t* dst = g_fmt + dstoff + (long)rb * 2048;
#pragma unroll
    for (int i = 0; i < 16; i++) {
        int idx = i * 128 + t;
        int slot = idx & 3;
        int lane = (idx >> 2) & 31;
        int nig  = idx >> 7;                       // 0..15
        int n = ny * 128 + nig * 8 + (lane >> 2);
        int khalf = slot & 1;
        int k0 = kb * 16 + khalf * 8 + (lane & 3) * 2;
        float v0 = (k0 < K)     ? W[(long)k0 * 256 + n]       : 0.f;
        float v1 = (k0 + 1 < K) ? W[(long)(k0 + 1) * 256 + n] : 0.f;
        __half h0, l0, h1, l1;
        split_f16(v0, h0, l0);
        split_f16(v1, h1, l1);
        __half2 p = (slot >> 1) ? __halves2half2(l0, l1) : __halves2half2(h0, h1);
        dst[idx] = *(uint32_t*)&p;
    }
}

// ================= mma.sync fp16x3 GEMM with dynamic scaling =================
// C[M,256] = op(A)[M,K] @ B[K,256]; CTA: 128 rows x 128 cols.
// GRID: x = n-half (0/1), y = m-block  --> the two n-halves of one m-block are
// ADJACENT in launch order, so their identical A-row (gather) reads hit L2.
// 256 threads = 8 warps, layout 4 (m) x 2 (n): warp tile 32x64.
// __launch_bounds__(256,2) pins regs <= 128 so 2 CTAs co-reside per SM.
// compute() hoists ALL fragment LDS up front; 48 mma in 3 passes (ILP).
// A scaled by 1/s at staging (s = sum(g_amax)/32768), mask-truncation split.
// kb3 = leading k-blocks with the full 3-term split; kb >= kb3 -> 1-term.
// MODE 0: plain A scalar loads (ragged K), relu
// MODE 1: A = ma[b2a[r]] - mbprev[b2revb[r]] (K=256), relu(addp + C)
// MODE 2: A from 3 sources (K=768), plain store
// MODE 3: plain A (K=256), relu(C + bias)
template<int MODE>
__global__ __launch_bounds__(256, 2)
void gemm_mma(const float* __restrict__ Ap, const float* __restrict__ A2,
              const float* __restrict__ A3,
              const int* __restrict__ gi1, const int* __restrict__ gi2,
              const uint32_t* __restrict__ fmt,
              float* __restrict__ Cp, const float* __restrict__ addp,
              const float* __restrict__ biasp, int M, int K, int KB, int kb3,
              int sa, int sb, int sc, int out_slot)
{
    // A fragments: hi plane [0..1023], lo plane [1024..2047]; idx=(mig*32+lane)*4+reg
    __shared__ uint32_t As[2][2048];
    // B fragments: idx=(nig*32+lane)*4+slot
    __shared__ uint32_t Bs[2][2048];
    __shared__ float red[8];

    const int tid = threadIdx.x;
    const int lane = tid & 31;
    const int wid = tid >> 5;
    const int wm = wid & 3;          // 0..3 (m groups of 32 rows)
    const int wn = wid >> 2;         // 0..1 (n halves of 64 cols)
    const int m0 = blockIdx.y * 128;
    const int n0 = blockIdx.x * 128;
    const int nhalf = blockIdx.x;

    // dynamic scale
    float s = 1.f, inv_s = 1.f;
    if (sa >= 0) {
        float sum = __int_as_float(g_amax[sa]);
        if (sb >= 0) sum += __int_as_float(g_amax[sb]);
        if (sc >= 0) sum += __int_as_float(g_amax[sc]);
        s = fmaxf(sum, 1e-20f) * (1.f / 32768.f);
        inv_s = 1.f / s;
    }

    // staging identity: thread stages row srow, k-half skh (8 k each)
    const int srow = tid >> 1;
    const int skh = tid & 1;
    const int gm_s = min(m0 + srow, M - 1);
    int ia = 0, ir = 0;
    if (MODE == 1) { ia = gi1[gm_s]; ir = gi2[gm_s]; }

    // STS base u32-index; the 4 staged pairs land at sts0 + 4*t
    const int sts0 = (((srow >> 4) * 32 + ((srow & 7) << 2)) * 4)
                   + (skh * 2 + ((srow >> 3) & 1));

    float acc[2][8][4];
#pragma unroll
    for (int mi = 0; mi < 2; mi++)
#pragma unroll
        for (int ni = 0; ni < 8; ni++)
#pragma unroll
            for (int q = 0; q < 4; q++) acc[mi][ni][q] = 0.f;

    float areg[8];

    auto loadA = [&](int kb) {
        const int kbase = kb * 16 + skh * 8;
        if (MODE == 0) {
            const float* row = Ap + (long)gm_s * K + kbase;
#pragma unroll
            for (int j = 0; j < 8; j++) areg[j] = (kbase + j < K) ? row[j] * inv_s : 0.f;
        } else if (MODE == 1) {
            const float* ra = Ap + ((long)ia << 8) + kbase;
            const float* rr = A2 + ((long)ir << 8) + kbase;
            float4 x0 = *(const float4*)ra, x1 = *(const float4*)(ra + 4);
            float4 y0 = *(const float4*)rr, y1 = *(const float4*)(rr + 4);
            areg[0] = (x0.x - y0.x) * inv_s; areg[1] = (x0.y - y0.y) * inv_s;
            areg[2] = (x0.z - y0.z) * inv_s; areg[3] = (x0.w - y0.w) * inv_s;
            areg[4] = (x1.x - y1.x) * inv_s; areg[5] = (x1.y - y1.y) * inv_s;
            areg[6] = (x1.z - y1.z) * inv_s; areg[7] = (x1.w - y1.w) * inv_s;
        } else if (MODE == 2) {
            int which = kb >> 4;
            const float* src = (which == 0) ? Ap : (which == 1) ? A2 : A3;
            const float* ra = src + ((long)gm_s << 8) + (kb & 15) * 16 + skh * 8;
            float4 x0 = *(const float4*)ra, x1 = *(const float4*)(ra + 4);
            areg[0] = x0.x * inv_s; areg[1] = x0.y * inv_s;
            areg[2] = x0.z * inv_s; areg[3] = x0.w * inv_s;
            areg[4] = x1.x * inv_s; areg[5] = x1.y * inv_s;
            areg[6] = x1.z * inv_s; areg[7] = x1.w * inv_s;
        } else {
            const float* ra = Ap + ((long)gm_s << 8) + kbase;
            float4 x0 = *(const float4*)ra, x1 = *(const float4*)(ra + 4);
            areg[0] = x0.x * inv_s; areg[1] = x0.y * inv_s;
            areg[2] = x0.z * inv_s; areg[3] = x0.w * inv_s;
            areg[4] = x1.x * inv_s; areg[5] = x1.y * inv_s;
            areg[6] = x1.z * inv_s; areg[7] = x1.w * inv_s;
        }
    };

    auto issueB = [&](int kb, int buf) {
        const float4* src = (const float4*)(fmt + (long)(nhalf * KB + kb) * 2048);
        uint32_t dst = smem_u32(&Bs[buf][0]);
#pragma unroll
        for (int i = 0; i < 2; i++) {
            int idx = i * 256 + tid;
            cp16(dst + idx * 16, src + idx);
        }
        asm volatile("cp.async.commit_group;" ::: "memory");
    };

    // mask-truncation split: hi = x with low 13 mantissa bits zeroed (exact f16),
    // lo = x - hi (one FADD). Packed pairs via single pack-convert.
    auto storeA = [&](int buf) {
#pragma unroll
        for (int t = 0; t < 4; t++) {
            float x0 = areg[t * 2 + 0];
            float x1 = areg[t * 2 + 1];
            float h0 = __uint_as_float(__float_as_uint(x0) & 0xFFFFE000u);
            float h1 = __uint_as_float(__float_as_uint(x1) & 0xFFFFE000u);
            __half2 ph = __floats2half2_rn(h0, h1);
            __half2 pl = __floats2half2_rn(x0 - h0, x1 - h1);
            As[buf][sts0 + 4 * t]        = *(uint32_t*)&ph;
            As[buf][1024 + sts0 + 4 * t] = *(uint32_t*)&pl;
        }
    };

    // 3-pass compute: hoisted loads, same-acc mma separated by 15 others.
    auto compute = [&](int buf, bool full3) {
        const uint32_t* a_s = As[buf];
        const uint32_t* b_s = Bs[buf];
        uint4 bf[8];
#pragma unroll
        for (int ni = 0; ni < 8; ni++)
            bf[ni] = *(const uint4*)(b_s + ((wn * 8 + ni) * 32 + lane) * 4);
        uint4 ah4[2], al4[2];
#pragma unroll
        for (int mi = 0; mi < 2; mi++) {
            int mig = wm * 2 + mi;
            ah4[mi] = *(const uint4*)(a_s + (mig * 32 + lane) * 4);
            if (full3)
                al4[mi] = *(const uint4*)(a_s + 1024 + (mig * 32 + lane) * 4);
        }
        // pass 1: ah * bh
#pragma unroll
        for (int ni = 0; ni < 8; ni++) {
            uint32_t bh[2] = {bf[ni].x, bf[ni].y};
#pragma unroll
            for (int mi = 0; mi < 2; mi++) {
                uint32_t a[4] = {ah4[mi].x, ah4[mi].y, ah4[mi].z, ah4[mi].w};
                mma_f16(acc[mi][ni], a, bh);
            }
        }
        if (full3) {
            // pass 2: ah * bl
#pragma unroll
            for (int ni = 0; ni < 8; ni++) {
                uint32_t bl[2] = {bf[ni].z, bf[ni].w};
#pragma unroll
                for (int mi = 0; mi < 2; mi++) {
                    uint32_t a[4] = {ah4[mi].x, ah4[mi].y, ah4[mi].z, ah4[mi].w};
                    mma_f16(acc[mi][ni], a, bl);
                }
            }
            // pass 3: al * bh
#pragma unroll
            for (int ni = 0; ni < 8; ni++) {
                uint32_t bh[2] = {bf[ni].x, bf[ni].y};
#pragma unroll
                for (int mi = 0; mi < 2; mi++) {
                    uint32_t a[4] = {al4[mi].x, al4[mi].y, al4[mi].z, al4[mi].w};
                    mma_f16(acc[mi][ni], a, bh);
                }
            }
        }
    };

    // prologue
    loadA(0);
    issueB(0, 0);
    storeA(0);
    asm volatile("cp.async.wait_group 0;" ::: "memory");
    __syncthreads();

    for (int kb = 0; kb < KB; kb++) {
        const int buf = kb & 1;
        const bool more = (kb + 1 < KB);
        if (more) { loadA(kb + 1); issueB(kb + 1, buf ^ 1); }
        compute(buf, kb < kb3);
        if (more) {
            storeA(buf ^ 1);
            asm volatile("cp.async.wait_group 0;" ::: "memory");
        }
        __syncthreads();
    }

    // epilogue (scale back by s, fused add/bias/relu, track output amax)
    float wmax = 0.f;
#pragma unroll
    for (int mi = 0; mi < 2; mi++) {
        int r0 = m0 + wm * 32 + mi * 16 + (lane >> 2);
#pragma unroll
        for (int ni = 0; ni < 8; ni++) {
            int c = n0 + wn * 64 + ni * 8 + (lane & 3) * 2;
#pragma unroll
            for (int half = 0; half < 2; half++) {
                int r = r0 + half * 8;
                if (r >= M) continue;
                float x = acc[mi][ni][half * 2 + 0] * s;
                float y = acc[mi][ni][half * 2 + 1] * s;
                long o = (long)r * 256 + c;
                if (MODE == 1) {
                    float2 t = *(const float2*)(addp + o);
                    x += t.x; y += t.y;
                }
                if (MODE == 3) {
                    float2 t = *(const float2*)(biasp + c);
                    x += t.x; y += t.y;
                }
                if (MODE != 2) { x = fmaxf(x, 0.f); y = fmaxf(y, 0.f); }
                wmax = fmaxf(wmax, fmaxf(fabsf(x), fabsf(y)));
                *(float2*)(Cp + o) = make_float2(x, y);
            }
        }
    }
    if (out_slot >= 0) block_amax(wmax, red, out_slot);
}

// ---------------- sum*max neighbor aggregation (+ amax tracking) ----------
template<bool ADD>
__global__ __launch_bounds__(256)
void sum_max_kernel(const float* __restrict__ mb, const int* __restrict__ a2b,
                    const float* __restrict__ addsrc, float* __restrict__ outp,
                    int out_slot)
{
    __shared__ float red[8];
    int a = blockIdx.x * 4 + (threadIdx.x >> 6);
    float wmax = 0.f;
    if (a < A_N) {
        int h = (threadIdx.x & 63) << 2;
        const int* ab = a2b + (long)a * NBN;
        float4 s = make_float4(0.f, 0.f, 0.f, 0.f);
        float4 mx = make_float4(-1e30f, -1e30f, -1e30f, -1e30f);
#pragma unroll
        for (int j = 0; j < NBN; j++) {
            float4 v = *(const float4*)(mb + (long)ab[j] * H + h);
            s.x += v.x; s.y += v.y; s.z += v.z; s.w += v.w;
            mx.x = fmaxf(mx.x, v.x); mx.y = fmaxf(mx.y, v.y);
            mx.z = fmaxf(mx.z, v.z); mx.w = fmaxf(mx.w, v.w);
        }
        long o = (long)a * H + h;
        float4 r = make_float4(s.x * mx.x, s.y * mx.y, s.z * mx.z, s.w * mx.w);
        if (ADD) {
            float4 c = *(const float4*)(addsrc + o);
            r.x += c.x; r.y += c.y; r.z += c.z; r.w += c.w;
        }
        *(float4*)(outp + o) = r;
        wmax = fmaxf(fmaxf(fabsf(r.x), fabsf(r.y)), fmaxf(fabsf(r.z), fabsf(r.w)));
    }
    block_amax(wmax, red, out_slot);
}

// ---------------- exclusive scan of molecule sizes ----------------
__global__ void scan_kernel(const int* __restrict__ sizes)
{
    __shared__ int part[1024];
    int t = threadIdx.x;
    const int CH = (M_N + 1023) / 1024;
    int base = t * CH;
    int s = 0;
    for (int i = 0; i < CH; i++) {
        int idx = base + i;
        if (idx < M_N) s += sizes[idx];
    }
    part[t] = s;
    __syncthreads();
    for (int off = 1; off < 1024; off <<= 1) {
        int v = (t >= off) ? part[t - off] : 0;
        __syncthreads();
        part[t] += v;
        __syncthreads();
    }
    int run = (t == 0) ? 0 : part[t - 1];
    for (int i = 0; i < CH; i++) {
        int idx = base + i;
        if (idx < M_N) { g_offsets[idx] = run; run += sizes[idx]; }
    }
}

// ---------------- per-molecule mean pooling ----------------
__global__ __launch_bounds__(64)
void pool_kernel(const float* __restrict__ ah, const int* __restrict__ sizes,
                 float* __restrict__ out)
{
    int m = blockIdx.x;
    int h = threadIdx.x << 2;
    int start = g_offsets[m];
    int n = sizes[m];
    float4 s = make_float4(0.f, 0.f, 0.f, 0.f);
    for (int i = 0; i < n; i++) {
        float4 v = *(const float4*)(ah + (long)(start + i) * H + h);
        s.x += v.x; s.y += v.y; s.z += v.z; s.w += v.w;
    }
    float inv = 1.0f / (float)n;
    *(float4*)(out + (long)m * H + h) = make_float4(s.x * inv, s.y * inv, s.z * inv, s.w * inv);
}

// ---------------- launch ----------------
extern "C" void kernel_launch(void* const* d_in, const int* in_sizes, int n_in,
                              void* d_out, int out_size)
{
    const float* f_atoms = (const float*)d_in[0];
    const float* f_bonds = (const float*)d_in[1];
    const float* W_ia    = (const float*)d_in[2];
    const float* W_ib    = (const float*)d_in[3];
    const float* W_h     = (const float*)d_in[4];
    const float* W_o     = (const float*)d_in[5];
    const float* b_o     = (const float*)d_in[6];
    const float* W_lr    = (const float*)d_in[7];
    const int*   a2b     = (const int*)d_in[8];
    const int*   b2a     = (const int*)d_in[9];
    const int*   b2revb  = (const int*)d_in[10];
    const int*   sizes   = (const int*)d_in[11];
    float* out = (float*)d_out;

    float *input_atom, *input_bond, *ma, *mb0, *mb1, *agg, *h1, *ah;
    uint32_t* fmt;
    cudaGetSymbolAddress((void**)&input_atom, g_input_atom);
    cudaGetSymbolAddress((void**)&input_bond, g_input_bond);
    cudaGetSymbolAddress((void**)&ma, g_message_atom);
    cudaGetSymbolAddress((void**)&mb0, g_mb0);
    cudaGetSymbolAddress((void**)&mb1, g_mb1);
    cudaGetSymbolAddress((void**)&agg, g_agg);
    cudaGetSymbolAddress((void**)&h1, g_h1);
    cudaGetSymbolAddress((void**)&ah, g_ah);
    cudaGetSymbolAddress((void**)&fmt, g_fmt);

    // weight prep (also zeroes g_amax in block 0): 262 regions, 2 launches
    prep_all<<<131, 128>>>(W_ia, W_ib, W_h, W_lr, W_o, 0);
    prep_all<<<131, 128>>>(W_ia, W_ib, W_h, W_lr, W_o, 131);

    // grid: x = n-half (adjacent in launch order -> L2 A-row reuse), y = m-block
    dim3 gA(2, cdiv(A_N, 128)), gB(2, cdiv(B_N, 128));

    // atom input projection: full 3-term (feeds ma at depth 0, before agg
    // dominates -> its error rides the full recurrence; R16 showed 1-term
    // here costs ~4e-4 on the output)
    gemm_mma<0><<<gA, 256>>>(f_atoms, nullptr, nullptr, nullptr, nullptr,
                             fmt + OFF_WIA, input_atom, nullptr, nullptr,
                             A_N, FA, 9, 9, -1, -1, -1, 8);
    // bond input projection: full 3-term (base of the amplifying recurrence)
    gemm_mma<0><<<gB, 256>>>(f_bonds, nullptr, nullptr, nullptr, nullptr,
                             fmt + OFF_WIB, input_bond, nullptr, nullptr,
                             B_N, FB, 10, 10, -1, -1, -1, 0);

    // message passing (ping-pong bond buffers), full 3-term fp16
    const float* mbcur = input_bond;
    for (int d = 0; d < DEPTH - 1; d++) {
        // ma amax -> slot 3+d
        sum_max_kernel<true><<<cdiv(A_N, 4), 256>>>(mbcur, a2b,
                                                    (d == 0) ? input_atom : ma, ma, 3 + d);
        float* mbout = (d % 2 == 0) ? mb0 : mb1;
        int mb_slot_in = (d == 0) ? 0 : d;           // ib=0, mb_l0=1, mb_l1=2
        int mb_slot_out = (d < 2) ? (1 + d) : -1;    // mb amax for next layer
        gemm_mma<1><<<gB, 256>>>(ma, mbcur, nullptr, b2a, b2revb,
                                 fmt + OFF_WH + (long)d * 65536,
                                 mbout, input_bond, nullptr,
                                 B_N, H, 16, 16, 3 + d, mb_slot_in, -1, mb_slot_out);
        mbcur = mbout;
    }

    // final aggregation -> agg amax slot 6
    sum_max_kernel<false><<<cdiv(A_N, 4), 256>>>(mbcur, a2b, nullptr, agg, 6);

    // W_lr GEMM: scale = (agg + ma + ia)/32768; 3-term for agg slice (kb<16),
    // 1-term for the magnitude-dominated ma/ia slices
    gemm_mma<2><<<gA, 256>>>(agg, ma, input_atom, nullptr, nullptr,
                             fmt + OFF_WLR, h1, nullptr, nullptr,
                             A_N, 3 * H, 48, 16, 6, 5, 8, 7);

    // W_o GEMM: final linear stage — 1-term fp16 (error passes unamplified)
    gemm_mma<3><<<gA, 256>>>(h1, nullptr, nullptr, nullptr, nullptr,
                             fmt + OFF_WO, ah, nullptr, b_o,
                             A_N, H, 16, 0, 7, -1, -1, -1);

    scan_kernel<<<1, 1024>>>(sizes);
    pool_kernel<<<M_N, 64>>>(ah, sizes, out);
}